// round 15
// baseline (speedup 1.0000x reference)
#include <cuda_runtime.h>
#include <cuda_fp16.h>
#include <math.h>

#define NN   1024
#define DNF  128
#define G3   384
#define ALD  136
#define GLD  388
#define GB_LD 132
#define LOG2E 1.4426950408889634f
#define NBLK 64

// ---------------- device scratch ----------------
__device__ float g_er  [NN * DNF];
__device__ float g_cei [NN * G3];
__device__ float g_ha  [NN * DNF];
__device__ float g_hb  [NN * DNF];
__device__ __half g_wimH[G3 * DNF];
__device__ __half g_wieH[G3 * DNF];
__device__ __half g_whhH[G3 * DNF];
__device__ __half g_wgH [DNF * 256];
__device__ __half g_woH [DNF * 256];
__device__ float g_bvec[G3];
__device__ int2  g_nze [NN * NN];
__device__ int   g_nzc [NN];
__device__ float g_part[NBLK * DNF];
__device__ int   g_rc;
__device__ int   g_arr [NBLK];

// ---------------- fast transcendentals --------
__device__ __forceinline__ float fex2(float x) {
    float r; asm("ex2.approx.f32 %0, %1;" : "=f"(r) : "f"(x)); return r;
}
__device__ __forceinline__ float frcp(float x) {
    float r; asm("rcp.approx.f32 %0, %1;" : "=f"(r) : "f"(x)); return r;
}
__device__ __forceinline__ float sigf(float x) {
    return frcp(1.0f + fex2(-x * LOG2E));
}
__device__ __forceinline__ float tanhf_fast(float x) {
    return 1.0f - 2.0f * frcp(1.0f + fex2(x * (2.0f * LOG2E)));
}

__device__ __forceinline__ void mma_f16(float* c,
                                        unsigned a0, unsigned a1,
                                        unsigned a2, unsigned a3,
                                        unsigned b0, unsigned b1) {
    asm volatile(
        "mma.sync.aligned.m16n8k16.row.col.f32.f16.f16.f32 "
        "{%0,%1,%2,%3}, {%4,%5,%6,%7}, {%8,%9}, {%0,%1,%2,%3};"
        : "+f"(c[0]), "+f"(c[1]), "+f"(c[2]), "+f"(c[3])
        : "r"(a0), "r"(a1), "r"(a2), "r"(a3), "r"(b0), "r"(b1));
}

// fp16 frag-packed index (round-11 layout)
__device__ __forceinline__ int hidx(int n, int k, int nfr) {
    int f = n >> 3, q = n & 7;
    int t = k >> 4, kk = k & 15;
    int half = kk >> 3;
    int r = (kk & 7) >> 1;
    int lo = kk & 1;
    int u = t >> 1, tk = t & 1;
    return ((((u * nfr + f) * 32 + q * 4 + r) * 4) + tk * 2 + half) * 2 + lo;
}

// flag-array grid barrier: monotonic tags within one kernel run.
// Slots reset after final use (before readout); replays serialize on kernel end.
__device__ __forceinline__ void gbar2(int tag) {
    __syncthreads();
    if (threadIdx.x == 0) {
        __threadfence();
        ((volatile int*)g_arr)[blockIdx.x] = tag;
    }
    if (threadIdx.x < NBLK) {
        while (((volatile int*)g_arr)[threadIdx.x] < tag) { }
    }
    __syncthreads();
    __threadfence();   // acquire: flush L1 before reading peers' data
}

// strided warp gather (stride 2, start = half) over interleaved (idx,val)
__device__ __forceinline__ float4 gather_half(const float* __restrict__ src,
                                              const int2* __restrict__ ep,
                                              int cnt, int lane, int half) {
    float4 acc = make_float4(0.f, 0.f, 0.f, 0.f);
    int k = half;
    for (; k + 6 < cnt; k += 8) {
        int2 e0 = ep[k], e1 = ep[k + 2], e2 = ep[k + 4], e3 = ep[k + 6];
        float w0 = __int_as_float(e0.y), w1 = __int_as_float(e1.y);
        float w2 = __int_as_float(e2.y), w3 = __int_as_float(e3.y);
        float4 a0 = *(const float4*)(src + (size_t)e0.x * DNF + lane * 4);
        float4 a1 = *(const float4*)(src + (size_t)e1.x * DNF + lane * 4);
        float4 a2 = *(const float4*)(src + (size_t)e2.x * DNF + lane * 4);
        float4 a3 = *(const float4*)(src + (size_t)e3.x * DNF + lane * 4);
        acc.x += w0*a0.x + w1*a1.x + w2*a2.x + w3*a3.x;
        acc.y += w0*a0.y + w1*a1.y + w2*a2.y + w3*a3.y;
        acc.z += w0*a0.z + w1*a1.z + w2*a2.z + w3*a3.z;
        acc.w += w0*a0.w + w1*a1.w + w2*a2.w + w3*a3.w;
    }
    for (; k < cnt; k += 2) {
        int2 e = ep[k];
        float w = __int_as_float(e.y);
        float4 av = *(const float4*)(src + (size_t)e.x * DNF + lane * 4);
        acc.x += w*av.x; acc.y += w*av.y; acc.z += w*av.z; acc.w += w*av.w;
    }
    return acc;
}

// ---------------------------------------------------------------------------
// phase 0: setup. warps 0-15: adjacency compaction + e-reduce (warp/row).
// warps 16-31: weight products with B-reuse + fp16 packing + bvec.
// ---------------------------------------------------------------------------
__device__ __forceinline__ void setup_body(
        const float* __restrict__ adj, const float* __restrict__ e,
        const float* __restrict__ w_msg_h, const float* __restrict__ w_msg_e,
        const float* __restrict__ w_ih, const float* __restrict__ b_msg,
        const float* __restrict__ w_hh, const float* __restrict__ w_gate,
        const float* __restrict__ w_out) {
    const int tid  = threadIdx.x;
    const int lane = tid & 31;
    const int w    = tid >> 5;
    const int bid  = blockIdx.x;

    if (w < 16) {
        // ---- adjacency compaction (warp per row) ----
        const int row = bid * 16 + w;
        const float* arow = adj + (size_t)row * NN;
        const unsigned lm = (1u << lane) - 1u;
        int2* ep = g_nze + (size_t)row * NN;
        int off = 0;
        for (int c = 0; c < 32; c++) {
            float v = arow[c * 32 + lane];
            unsigned m = __ballot_sync(0xffffffffu, v != 0.0f);
            if (v != 0.0f) {
                int p = off + __popc(m & lm);
                ep[p] = make_int2(c * 32 + lane, __float_as_int(v));
            }
            off += __popc(m);
        }
        if (lane == 0) g_nzc[row] = off;
        __syncwarp();

        // ---- e-reduce: er[row,:] = sum_k val_k * e[row, idx_k, :] ----
        const int cnt = off;
        const float* eb = e + (size_t)row * NN * DNF;
        float4 acc = make_float4(0.f, 0.f, 0.f, 0.f);
        int k = 0;
        for (; k + 8 <= cnt; k += 8) {
            int2 ee[8];
#pragma unroll
            for (int u = 0; u < 8; u++) ee[u] = ep[k + u];
            float4 a[8];
#pragma unroll
            for (int u = 0; u < 8; u++)
                a[u] = *(const float4*)(eb + (size_t)ee[u].x * DNF + lane * 4);
#pragma unroll
            for (int u = 0; u < 8; u++) {
                float vv = __int_as_float(ee[u].y);
                acc.x += vv * a[u].x; acc.y += vv * a[u].y;
                acc.z += vv * a[u].z; acc.w += vv * a[u].w;
            }
        }
        for (; k < cnt; k++) {
            int2 e1 = ep[k];
            float vv = __int_as_float(e1.y);
            float4 av = *(const float4*)(eb + (size_t)e1.x * DNF + lane * 4);
            acc.x += vv*av.x; acc.y += vv*av.y; acc.z += vv*av.z; acc.w += vv*av.w;
        }
        *(float4*)(g_er + (size_t)row * DNF + lane * 4) = acc;
    } else {
        // ---- weight products: wim/wie, B-reuse tiling ----
        // global weight-warp id 0..1023; matrix m = ww>>9; widx = ww&511
        // n-tile = widx>>2 (3 rows), k-chunk = widx&3 (32 cols)
        const int ww = bid * 16 + (w - 16);
        const int m  = ww >> 9;
        const int widx = ww & 511;
        const int n0 = (widx >> 2) * 3;
        const int kk = (widx & 3) * 32 + lane;
        const float* B = m ? w_msg_e : w_msg_h;
        __half* P = m ? g_wieH : g_wimH;
        const float* w0 = w_ih + (size_t)(n0 + 0) * DNF;
        const float* w1 = w_ih + (size_t)(n0 + 1) * DNF;
        const float* w2 = w_ih + (size_t)(n0 + 2) * DNF;
        float a0 = 0.f, a1 = 0.f, a2 = 0.f;
#pragma unroll 4
        for (int d = 0; d < DNF; d++) {
            float bb = B[(size_t)d * DNF + kk];
            a0 += w0[d] * bb;
            a1 += w1[d] * bb;
            a2 += w2[d] * bb;
        }
        P[hidx(n0 + 0, kk, 48)] = __float2half_rn(a0);
        P[hidx(n0 + 1, kk, 48)] = __float2half_rn(a1);
        P[hidx(n0 + 2, kk, 48)] = __float2half_rn(a2);

        // ---- packs: gwt in 0..32767 ----
        const int gwt = bid * 512 + (tid - 512);
        // whh: 49152 elements
        for (int ii = gwt; ii < G3 * DNF; ii += 32768) {
            int n = ii >> 7, k2 = ii & 127;
            g_whhH[hidx(n, k2, 48)] = __float2half_rn(w_hh[(size_t)n * DNF + k2]);
        }
        // wg / wo: 32768 each
        {
            int n = gwt >> 8, k2 = gwt & 255;
            g_wgH[hidx(n, k2, 16)] = __float2half_rn(w_gate[(size_t)n * 256 + k2]);
            g_woH[hidx(n, k2, 16)] = __float2half_rn(w_out[(size_t)n * 256 + k2]);
        }
        // bvec
        if (gwt < G3) {
            float acc = 0.f;
            const float* wr = w_ih + (size_t)gwt * DNF;
#pragma unroll 4
            for (int k2 = 0; k2 < DNF; k2++) acc += wr[k2] * b_msg[k2];
            g_bvec[gwt] = acc;
        }
    }
}

// ---------------------------------------------------------------------------
// cei phase (round-14 body)
// ---------------------------------------------------------------------------
__device__ __forceinline__ void cei_body(char* S) {
    __half* sA  = (__half*)S;
    float*  red = (float*)(S + 4352);

    const int tid  = threadIdx.x;
    const int lane = tid & 31;
    const int w    = tid >> 5;
    const int nw   = w & 15;
    const int kh   = w >> 4;
    const int q    = lane >> 2, r = lane & 3;
    const int r0   = blockIdx.x * 16;

#pragma unroll
    for (int rep = 0; rep < 2; rep++) {
        int eid = tid + rep * 1024;
        int i = eid >> 7, d = eid & 127;
        sA[i * ALD + d] = __float2half_rn(g_er[(size_t)(r0 + i) * DNF + d]);
    }
    __syncthreads();

    const unsigned* Aw = (const unsigned*)sA;

    float acc[3][4];
#pragma unroll
    for (int j = 0; j < 3; j++)
#pragma unroll
        for (int c = 0; c < 4; c++) acc[j][c] = 0.f;

    const uint4* bp = (const uint4*)g_wieH;

    uint4 bf[2][3];
#pragma unroll
    for (int j = 0; j < 3; j++)
        bf[0][j] = bp[((kh * 2) * 48 + nw * 3 + j) * 32 + lane];

#pragma unroll
    for (int kk = 0; kk < 2; kk++) {
        const int u = kh * 2 + kk;
        const int cur = kk & 1, nxt = cur ^ 1;
        if (kk < 1) {
#pragma unroll
            for (int j = 0; j < 3; j++)
                bf[nxt][j] = bp[((u + 1) * 48 + nw * 3 + j) * 32 + lane];
        }
#pragma unroll
        for (int tk = 0; tk < 2; tk++) {
            const int off = (u * 2 + tk) * 8;
            unsigned a0 = Aw[q * 68 + off + r];
            unsigned a1 = Aw[(q + 8) * 68 + off + r];
            unsigned a2 = Aw[q * 68 + off + 4 + r];
            unsigned a3 = Aw[(q + 8) * 68 + off + 4 + r];
#pragma unroll
            for (int j = 0; j < 3; j++) {
                unsigned b0 = tk ? bf[cur][j].z : bf[cur][j].x;
                unsigned b1 = tk ? bf[cur][j].w : bf[cur][j].y;
                mma_f16(acc[j], a0, a1, a2, a3, b0, b1);
            }
        }
    }

    if (kh == 1) {
        float* rp = red + (nw * 32 + lane) * 13;
#pragma unroll
        for (int j = 0; j < 3; j++)
#pragma unroll
            for (int c = 0; c < 4; c++) rp[j * 4 + c] = acc[j][c];
    }
    __syncthreads();
    if (kh == 0) {
        const float* rp = red + (nw * 32 + lane) * 13;
#pragma unroll
        for (int j = 0; j < 3; j++) {
#pragma unroll
            for (int c = 0; c < 4; c++) acc[j][c] += rp[j * 4 + c];
            int col = (nw * 3 + j) * 8 + 2 * r;
            float bv0 = g_bvec[col], bv1 = g_bvec[col + 1];
            *(float2*)(g_cei + (size_t)(r0 + q) * G3 + col) =
                make_float2(acc[j][0] + bv0, acc[j][1] + bv1);
            *(float2*)(g_cei + (size_t)(r0 + q + 8) * G3 + col) =
                make_float2(acc[j][2] + bv0, acc[j][3] + bv1);
        }
    }
}

// ---------------------------------------------------------------------------
// layer phase (round-14 body)
// ---------------------------------------------------------------------------
__device__ __forceinline__ void layer_body(char* S,
                                           const float* __restrict__ hprev,
                                           float* __restrict__ hnext,
                                           const float* __restrict__ b_ih,
                                           const float* __restrict__ b_hh) {
    __half* shA = (__half*)S;
    __half* hhA = (__half*)S + 16 * ALD;
    float*  gbi = (float*)S;
    float*  G   = (float*)(S + 8704);
    float4* ph  = (float4*)G;

    const int tid  = threadIdx.x;
    const int lane = tid & 31;
    const int w    = tid >> 5;
    const int q    = lane >> 2, r = lane & 3;
    const int r0   = blockIdx.x * 16;

    {
        const int row  = r0 + (w & 15);
        const int half = w >> 4;
        const int cnt  = g_nzc[row];
        const int2* ep = g_nze + (size_t)row * NN;
        ph[w * 32 + lane] = gather_half(hprev, ep, cnt, lane, half);
    }
    __syncthreads();

    if (w < 16) {
        float4 a = ph[w * 32 + lane];
        float4 b = ph[(w + 16) * 32 + lane];
        __half2* rp = (__half2*)(shA + w * ALD);
        rp[lane * 2]     = __floats2half2_rn(a.x + b.x, a.y + b.y);
        rp[lane * 2 + 1] = __floats2half2_rn(a.z + b.z, a.w + b.w);
    } else {
        int row = r0 + (w - 16);
        float4 hv = *(const float4*)(hprev + (size_t)row * DNF + lane * 4);
        __half2* rp = (__half2*)(hhA + (w - 16) * ALD);
        rp[lane * 2]     = __floats2half2_rn(hv.x, hv.y);
        rp[lane * 2 + 1] = __floats2half2_rn(hv.z, hv.w);
    }
    __syncthreads();

    const int mat = w >> 4;
    const int nw  = w & 15;
    const unsigned* Aw = (const unsigned*)(mat ? hhA : shA);
    const uint4* bp = (const uint4*)(mat ? g_whhH : g_wimH);

    float acc[3][4];
#pragma unroll
    for (int j = 0; j < 3; j++)
#pragma unroll
        for (int c = 0; c < 4; c++) acc[j][c] = 0.f;

    uint4 bf[2][3];
#pragma unroll
    for (int j = 0; j < 3; j++)
        bf[0][j] = bp[(0 * 48 + nw * 3 + j) * 32 + lane];

#pragma unroll
    for (int u = 0; u < 4; u++) {
        const int cur = u & 1, nxt = cur ^ 1;
        if (u < 3) {
#pragma unroll
            for (int j = 0; j < 3; j++)
                bf[nxt][j] = bp[((u + 1) * 48 + nw * 3 + j) * 32 + lane];
        }
#pragma unroll
        for (int tk = 0; tk < 2; tk++) {
            const int off = (u * 2 + tk) * 8;
            unsigned a0 = Aw[q * 68 + off + r];
            unsigned a1 = Aw[(q + 8) * 68 + off + r];
            unsigned a2 = Aw[q * 68 + off + 4 + r];
            unsigned a3 = Aw[(q + 8) * 68 + off + 4 + r];
#pragma unroll
            for (int j = 0; j < 3; j++) {
                unsigned b0 = tk ? bf[cur][j].z : bf[cur][j].x;
                unsigned b1 = tk ? bf[cur][j].w : bf[cur][j].y;
                mma_f16(acc[j], a0, a1, a2, a3, b0, b1);
            }
        }
    }

    if (mat == 1) {
#pragma unroll
        for (int j = 0; j < 3; j++) {
            int col = (nw * 3 + j) * 8 + 2 * r;
            float b0 = b_hh[col], b1 = b_hh[col + 1];
            G[q * GLD + col]           = acc[j][0] + b0;
            G[q * GLD + col + 1]       = acc[j][1] + b1;
            G[(q + 8) * GLD + col]     = acc[j][2] + b0;
            G[(q + 8) * GLD + col + 1] = acc[j][3] + b1;
        }
    }
    __syncthreads();

    if (mat == 0) {
#pragma unroll
        for (int j = 0; j < 3; j++) {
            int col = (nw * 3 + j) * 8 + 2 * r;
            float bi0 = b_ih[col], bi1 = b_ih[col + 1];
#pragma unroll
            for (int s = 0; s < 2; s++) {
                int i = q + s * 8;
                int row = r0 + i;
                float2 ce = *(const float2*)(g_cei + (size_t)row * G3 + col);
                float gi0 = acc[j][s * 2 + 0] + ce.x + bi0;
                float gi1 = acc[j][s * 2 + 1] + ce.y + bi1;
                if (col < 256) {
                    G[i * GLD + col]     += gi0;
                    G[i * GLD + col + 1] += gi1;
                } else {
                    gbi[i * GB_LD + (col - 256)]     = gi0;
                    gbi[i * GB_LD + (col - 256) + 1] = gi1;
                }
            }
        }
    }
    __syncthreads();

#pragma unroll
    for (int rep = 0; rep < 2; rep++) {
        int eid = tid + rep * 1024;
        int i = eid >> 7, d = eid & 127;
        int row = r0 + i;
        float rr = sigf(G[i * GLD + d]);
        float zz = sigf(G[i * GLD + 128 + d]);
        float nn = tanhf_fast(gbi[i * GB_LD + d] + rr * G[i * GLD + 256 + d]);
        float hold = hprev[(size_t)row * DNF + d];
        hnext[(size_t)row * DNF + d] = (1.0f - zz) * nn + zz * hold;
    }
}

// ---------------------------------------------------------------------------
// readout phase (round-14 body)
// ---------------------------------------------------------------------------
__device__ __forceinline__ void readout_body(char* S,
        const float* __restrict__ hfin, const float* __restrict__ h0,
        const float* __restrict__ b_gate, const float* __restrict__ b_out,
        const float* __restrict__ w_embed, const float* __restrict__ edge,
        const float* __restrict__ w_fc, const float* __restrict__ b_fc,
        float* __restrict__ out, int* s_last) {
    float* sbuf = (float*)S;
    float* red  = (float*)(S + 16896);
    float* sred = (float*)(S + 35328);
    float* sgv  = (float*)(S + 39424);
    float* see  = (float*)(S + 39936);

    __half* hA0 = (__half*)sbuf;
    __half* hA1 = (__half*)sbuf + 16 * ALD;
    float* gp  = sbuf;
    float* op  = sbuf + 16 * GB_LD;

    const int tid  = threadIdx.x;
    const int lane = tid & 31;
    const int w    = tid >> 5;
    const int fg   = w & 7;
    const int mat  = (w >> 3) & 1;
    const int kh   = w >> 4;
    const int q    = lane >> 2, r = lane & 3;
    const int r0   = blockIdx.x * 16;

    {
        const float* src = (w < 16) ? hfin : h0;
        __half* dst = (w < 16) ? hA0 : hA1;
        int row = r0 + (w & 15);
        float4 v = *(const float4*)(src + (size_t)row * DNF + lane * 4);
        __half2* rp = (__half2*)(dst + (w & 15) * ALD);
        rp[lane * 2]     = __floats2half2_rn(v.x, v.y);
        rp[lane * 2 + 1] = __floats2half2_rn(v.z, v.w);
    }
    __syncthreads();

    const uint4* bp = (const uint4*)(mat ? g_woH : g_wgH);
    const unsigned* Aw = (const unsigned*)(kh ? hA1 : hA0);

    float acc[2][4];
#pragma unroll
    for (int j = 0; j < 2; j++)
#pragma unroll
        for (int c = 0; c < 4; c++) acc[j][c] = 0.f;

    uint4 bf[2][2];
#pragma unroll
    for (int j = 0; j < 2; j++)
        bf[0][j] = bp[((kh * 4) * 16 + fg * 2 + j) * 32 + lane];

#pragma unroll
    for (int kk = 0; kk < 4; kk++) {
        const int u = kh * 4 + kk;
        const int cur = kk & 1, nxt = cur ^ 1;
        if (kk < 3) {
#pragma unroll
            for (int j = 0; j < 2; j++)
                bf[nxt][j] = bp[((u + 1) * 16 + fg * 2 + j) * 32 + lane];
        }
#pragma unroll
        for (int tk = 0; tk < 2; tk++) {
            const int off = (kk * 2 + tk) * 8;
            unsigned a0 = Aw[q * 68 + off + r];
            unsigned a1 = Aw[(q + 8) * 68 + off + r];
            unsigned a2 = Aw[q * 68 + off + 4 + r];
            unsigned a3 = Aw[(q + 8) * 68 + off + 4 + r];
#pragma unroll
            for (int j = 0; j < 2; j++) {
                unsigned b0 = tk ? bf[cur][j].z : bf[cur][j].x;
                unsigned b1 = tk ? bf[cur][j].w : bf[cur][j].y;
                mma_f16(acc[j], a0, a1, a2, a3, b0, b1);
            }
        }
    }

    if (kh == 1) {
        float* rp = red + ((mat * 8 + fg) * 32 + lane) * 9;
#pragma unroll
        for (int j = 0; j < 2; j++)
#pragma unroll
            for (int c = 0; c < 4; c++) rp[j * 4 + c] = acc[j][c];
    }
    __syncthreads();
    if (kh == 0) {
        const float* rp = red + ((mat * 8 + fg) * 32 + lane) * 9;
        float* dst = mat ? op : gp;
        const float* bias = mat ? b_out : b_gate;
#pragma unroll
        for (int j = 0; j < 2; j++) {
#pragma unroll
            for (int c = 0; c < 4; c++) acc[j][c] += rp[j * 4 + c];
            int col = (fg * 2 + j) * 8 + 2 * r;
            float b0 = bias[col], b1 = bias[col + 1];
            dst[q * GB_LD + col]           = acc[j][0] + b0;
            dst[q * GB_LD + col + 1]       = acc[j][1] + b1;
            dst[(q + 8) * GB_LD + col]     = acc[j][2] + b0;
            dst[(q + 8) * GB_LD + col + 1] = acc[j][3] + b1;
        }
    }
    __syncthreads();

    {
        int grp = tid >> 7, d = tid & 127;
        float a = 0.f;
#pragma unroll
        for (int i = grp * 2; i < grp * 2 + 2; i++)
            a += sigf(gp[i * GB_LD + d]) * tanhf_fast(op[i * GB_LD + d]);
        sred[tid] = a;
    }
    __syncthreads();
    if (tid < 128) {
        float s = 0.f;
#pragma unroll
        for (int g = 0; g < 8; g++) s += sred[g * 128 + tid];
        g_part[blockIdx.x * DNF + tid] = s;
    }
    __syncthreads();

    if (tid == 0) {
        __threadfence();
        int old = atomicAdd(&g_rc, 1);
        *s_last = (old == NBLK - 1) ? 1 : 0;
        __threadfence();
    }
    __syncthreads();
    if (*s_last) {
        if (tid == 0) g_rc = 0;
        if (tid < 128) {
            float gv = 0.f;
            for (int b = 0; b < NBLK; b++) gv += g_part[b * DNF + tid];
            sgv[tid] = gv;
            float ee = 0.f;
#pragma unroll
            for (int f = 0; f < 5; f++) ee += w_embed[tid * 5 + f] * edge[f];
            see[tid] = ee;
        }
        __syncthreads();
        if (tid < 128) {
            float acc2 = b_fc[tid];
            const float* wr = w_fc + (size_t)tid * 256;
            for (int k = 0; k < 128; k++) acc2 += wr[k] * sgv[k];
            for (int k = 0; k < 128; k++) acc2 += wr[128 + k] * see[k];
            out[tid] = acc2;
        }
    }
}

// ---------------------------------------------------------------------------
// k_giga: setup | bar | cei | bar | 4x(layer | bar) | readout. 64 x 1024.
// ---------------------------------------------------------------------------
__global__ void __launch_bounds__(1024)
k_giga(const float* __restrict__ h_in,  const float* __restrict__ e,
       const float* __restrict__ adj,   const float* __restrict__ edge,
       const float* __restrict__ w_msg_h, const float* __restrict__ w_msg_e,
       const float* __restrict__ b_msg,
       const float* __restrict__ w_ih,  const float* __restrict__ w_hh,
       const float* __restrict__ b_ih,  const float* __restrict__ b_hh,
       const float* __restrict__ w_gate, const float* __restrict__ b_gate,
       const float* __restrict__ w_out, const float* __restrict__ b_out,
       const float* __restrict__ w_embed, const float* __restrict__ w_fc,
       const float* __restrict__ b_fc,  float* __restrict__ out) {
    __shared__ __align__(16) char S[40960];
    __shared__ int s_last;

    setup_body(adj, e, w_msg_h, w_msg_e, w_ih, b_msg, w_hh, w_gate, w_out);
    gbar2(1);

    cei_body(S);
    gbar2(2);

    const float* hp[4] = { h_in, g_ha, g_hb, g_ha };
    float*       hn[4] = { g_ha, g_hb, g_ha, g_hb };
#pragma unroll 1
    for (int l = 0; l < 4; l++) {
        layer_body(S, hp[l], hn[l], b_ih, b_hh);
        gbar2(3 + l);
    }

    // reset barrier slots for next replay (all blocks past all waits)
    if (threadIdx.x == 0) g_arr[blockIdx.x] = 0;

    readout_body(S, g_hb, h_in, b_gate, b_out, w_embed, edge,
                 w_fc, b_fc, out, &s_last);
}

// ---------------------------------------------------------------------------
extern "C" void kernel_launch(void* const* d_in, const int* in_sizes, int n_in,
                              void* d_out, int out_size) {
    const float* h_in    = (const float*)d_in[0];
    const float* e       = (const float*)d_in[1];
    const float* adj     = (const float*)d_in[2];
    const float* edge    = (const float*)d_in[3];
    const float* w_msg_h = (const float*)d_in[4];
    const float* w_msg_e = (const float*)d_in[5];
    const float* b_msg   = (const float*)d_in[6];
    const float* w_ih    = (const float*)d_in[7];
    const float* w_hh    = (const float*)d_in[8];
    const float* b_ih    = (const float*)d_in[9];
    const float* b_hh    = (const float*)d_in[10];
    const float* w_gate  = (const float*)d_in[11];
    const float* b_gate  = (const float*)d_in[12];
    const float* w_out   = (const float*)d_in[13];
    const float* b_out   = (const float*)d_in[14];
    const float* w_embed = (const float*)d_in[15];
    const float* w_fc    = (const float*)d_in[16];
    const float* b_fc    = (const float*)d_in[17];
    float* out = (float*)d_out;

    k_giga<<<NBLK, 1024>>>(h_in, e, adj, edge, w_msg_h, w_msg_e, b_msg,
                           w_ih, w_hh, b_ih, b_hh, w_gate, b_gate,
                           w_out, b_out, w_embed, w_fc, b_fc, out);
}

// round 16
// speedup vs baseline: 1.2122x; 1.2122x over previous
#include <cuda_runtime.h>
#include <cuda_fp16.h>
#include <math.h>

#define NN   1024
#define DNF  128
#define G3   384
#define ALD  136
#define GLD  388
#define GB_LD 132
#define LOG2E 1.4426950408889634f
#define NBLK 64

// ---------------- device scratch ----------------
__device__ float g_er  [NN * DNF];
__device__ float g_cei [NN * G3];
__device__ float g_ha  [NN * DNF];
__device__ float g_hb  [NN * DNF];
__device__ __half g_wimH[G3 * DNF];
__device__ __half g_wieH[G3 * DNF];
__device__ __half g_whhH[G3 * DNF];
__device__ __half g_wgH [DNF * 256];
__device__ __half g_woH [DNF * 256];
__device__ float g_bvec[G3];
__device__ int2  g_nze [NN * NN];
__device__ int   g_nzc [NN];
__device__ float g_part[NBLK * DNF];
__device__ int   g_rc;
__device__ int   g_bin [8];
__device__ int   g_bout[8];

// ---------------- fast transcendentals --------
__device__ __forceinline__ float fex2(float x) {
    float r; asm("ex2.approx.f32 %0, %1;" : "=f"(r) : "f"(x)); return r;
}
__device__ __forceinline__ float frcp(float x) {
    float r; asm("rcp.approx.f32 %0, %1;" : "=f"(r) : "f"(x)); return r;
}
__device__ __forceinline__ float sigf(float x) {
    return frcp(1.0f + fex2(-x * LOG2E));
}
__device__ __forceinline__ float tanhf_fast(float x) {
    return 1.0f - 2.0f * frcp(1.0f + fex2(x * (2.0f * LOG2E)));
}

__device__ __forceinline__ void mma_f16(float* c,
                                        unsigned a0, unsigned a1,
                                        unsigned a2, unsigned a3,
                                        unsigned b0, unsigned b1) {
    asm volatile(
        "mma.sync.aligned.m16n8k16.row.col.f32.f16.f16.f32 "
        "{%0,%1,%2,%3}, {%4,%5,%6,%7}, {%8,%9}, {%0,%1,%2,%3};"
        : "+f"(c[0]), "+f"(c[1]), "+f"(c[2]), "+f"(c[3])
        : "r"(a0), "r"(a1), "r"(a2), "r"(a3), "r"(b0), "r"(b1));
}

// fp16 frag-packed index (round-11 layout)
__device__ __forceinline__ int hidx(int n, int k, int nfr) {
    int f = n >> 3, q = n & 7;
    int t = k >> 4, kk = k & 15;
    int half = kk >> 3;
    int r = (kk & 7) >> 1;
    int lo = kk & 1;
    int u = t >> 1, tk = t & 1;
    return ((((u * nfr + f) * 32 + q * 4 + r) * 4) + tk * 2 + half) * 2 + lo;
}

// grid barrier across NBLK blocks (round-14 validated)
__device__ __forceinline__ void gbar(int k) {
    __syncthreads();
    if (threadIdx.x == 0) {
        __threadfence();
        atomicAdd(&g_bin[k], 1);
        while (((volatile int*)g_bin)[k] < NBLK) { }
        int o = atomicAdd(&g_bout[k], 1);
        if (o == NBLK - 1) { g_bin[k] = 0; g_bout[k] = 0; }
        __threadfence();
    }
    __syncthreads();
}

// strided warp gather (stride 2, start = half) over interleaved (idx,val)
__device__ __forceinline__ float4 gather_half(const float* __restrict__ src,
                                              const int2* __restrict__ ep,
                                              int cnt, int lane, int half) {
    float4 acc = make_float4(0.f, 0.f, 0.f, 0.f);
    int k = half;
    for (; k + 6 < cnt; k += 8) {
        int2 e0 = ep[k], e1 = ep[k + 2], e2 = ep[k + 4], e3 = ep[k + 6];
        float w0 = __int_as_float(e0.y), w1 = __int_as_float(e1.y);
        float w2 = __int_as_float(e2.y), w3 = __int_as_float(e3.y);
        float4 a0 = *(const float4*)(src + (size_t)e0.x * DNF + lane * 4);
        float4 a1 = *(const float4*)(src + (size_t)e1.x * DNF + lane * 4);
        float4 a2 = *(const float4*)(src + (size_t)e2.x * DNF + lane * 4);
        float4 a3 = *(const float4*)(src + (size_t)e3.x * DNF + lane * 4);
        acc.x += w0*a0.x + w1*a1.x + w2*a2.x + w3*a3.x;
        acc.y += w0*a0.y + w1*a1.y + w2*a2.y + w3*a3.y;
        acc.z += w0*a0.z + w1*a1.z + w2*a2.z + w3*a3.z;
        acc.w += w0*a0.w + w1*a1.w + w2*a2.w + w3*a3.w;
    }
    for (; k < cnt; k += 2) {
        int2 e = ep[k];
        float w = __int_as_float(e.y);
        float4 av = *(const float4*)(src + (size_t)e.x * DNF + lane * 4);
        acc.x += w*av.x; acc.y += w*av.y; acc.z += w*av.z; acc.w += w*av.w;
    }
    return acc;
}

// ---------------------------------------------------------------------------
// k_setup: bid<1024 — block/row compaction + 8-warp e-reduce (round-14 path).
// bid>=1024: 128 blocks weight products (B-reuse), 112 blocks packs, 1 bvec.
// ---------------------------------------------------------------------------
__global__ void __launch_bounds__(256)
k_setup(const float* __restrict__ adj, const float* __restrict__ e,
        const float* __restrict__ w_msg_h, const float* __restrict__ w_msg_e,
        const float* __restrict__ w_ih, const float* __restrict__ b_msg,
        const float* __restrict__ w_hh, const float* __restrict__ w_gate,
        const float* __restrict__ w_out) {
    const int bid = blockIdx.x;
    const int tid = threadIdx.x;

    if (bid < NN) {
        const int i    = bid;
        const int lane = tid & 31;
        const int w    = tid >> 5;

        __shared__ int   s_idx[NN];
        __shared__ float s_val[NN];
        __shared__ int   s_wcnt[8];
        __shared__ int   s_woff[8];
        __shared__ int   s_cnt;
        __shared__ float s_red[8 * DNF];

        const float* arow = adj + (size_t)i * NN;
        const int base = w * 128;

        float av[4]; unsigned mm[4];
#pragma unroll
        for (int c = 0; c < 4; c++) av[c] = arow[base + c * 32 + lane];
        int tot = 0;
#pragma unroll
        for (int c = 0; c < 4; c++) {
            mm[c] = __ballot_sync(0xffffffffu, av[c] != 0.0f);
            tot += __popc(mm[c]);
        }
        if (lane == 0) s_wcnt[w] = tot;
        __syncthreads();
        if (tid == 0) {
            int run = 0;
            for (int ww = 0; ww < 8; ww++) { s_woff[ww] = run; run += s_wcnt[ww]; }
            s_cnt = run;
        }
        __syncthreads();

        int off = s_woff[w];
        const unsigned lm = (1u << lane) - 1u;
#pragma unroll
        for (int c = 0; c < 4; c++) {
            if (av[c] != 0.0f) {
                int p = off + __popc(mm[c] & lm);
                s_idx[p] = base + c * 32 + lane;
                s_val[p] = av[c];
            }
            off += __popc(mm[c]);
        }
        __syncthreads();

        const int cnt = s_cnt;
        if (tid == 0) g_nzc[i] = cnt;
        for (int k = tid; k < cnt; k += 256)
            g_nze[(size_t)i * NN + k] = make_int2(s_idx[k],
                                                  __float_as_int(s_val[k]));

        const int q = tid & 31;
        const int g = tid >> 5;
        const float* ebase = e + (size_t)i * NN * DNF;
        float4 acc = make_float4(0.f, 0.f, 0.f, 0.f);
        for (int k = g; k < cnt; k += 8) {
            float v = s_val[k];
            float4 ev = *(const float4*)(ebase + (size_t)s_idx[k] * DNF + q * 4);
            acc.x += v * ev.x; acc.y += v * ev.y;
            acc.z += v * ev.z; acc.w += v * ev.w;
        }
        s_red[g * DNF + q * 4 + 0] = acc.x;
        s_red[g * DNF + q * 4 + 1] = acc.y;
        s_red[g * DNF + q * 4 + 2] = acc.z;
        s_red[g * DNF + q * 4 + 3] = acc.w;
        __syncthreads();
        if (tid < 128) {
            float s = 0.f;
#pragma unroll
            for (int gg = 0; gg < 8; gg++) s += s_red[gg * DNF + tid];
            g_er[(size_t)i * DNF + tid] = s;
        }
        return;
    }

    const int sid = bid - NN;
    if (sid < 128) {
        // ---- wim/wie products, B-reuse: warp owns 3 n-rows x 32 k-cols ----
        const int lane = tid & 31;
        const int w    = tid >> 5;              // 8 warps
        const int ww   = sid * 8 + w;           // 0..1023
        const int m    = ww >> 9;
        const int widx = ww & 511;
        const int n0   = (widx >> 2) * 3;
        const int kk   = (widx & 3) * 32 + lane;
        const float* B = m ? w_msg_e : w_msg_h;
        __half* P = m ? g_wieH : g_wimH;
        const float* w0 = w_ih + (size_t)(n0 + 0) * DNF;
        const float* w1 = w_ih + (size_t)(n0 + 1) * DNF;
        const float* w2 = w_ih + (size_t)(n0 + 2) * DNF;
        float a0 = 0.f, a1 = 0.f, a2 = 0.f;
#pragma unroll 4
        for (int d = 0; d < DNF; d++) {
            float bb = B[(size_t)d * DNF + kk];
            a0 += w0[d] * bb;
            a1 += w1[d] * bb;
            a2 += w2[d] * bb;
        }
        P[hidx(n0 + 0, kk, 48)] = __float2half_rn(a0);
        P[hidx(n0 + 1, kk, 48)] = __float2half_rn(a1);
        P[hidx(n0 + 2, kk, 48)] = __float2half_rn(a2);
    } else if (sid < 176) {
        int b = sid - 128;                       // 48 blocks
#pragma unroll
        for (int rep = 0; rep < 4; rep++) {
            int eid = b * 1024 + rep * 256 + tid;
            int n = eid >> 7, k = eid & 127;
            g_whhH[hidx(n, k, 48)] = __float2half_rn(w_hh[(size_t)n * DNF + k]);
        }
    } else if (sid < 208) {
        int b = sid - 176;                       // 32 blocks
#pragma unroll
        for (int rep = 0; rep < 4; rep++) {
            int eid = b * 1024 + rep * 256 + tid;
            int n = eid >> 8, k = eid & 255;
            g_wgH[hidx(n, k, 16)] = __float2half_rn(w_gate[(size_t)n * 256 + k]);
        }
    } else if (sid < 240) {
        int b = sid - 208;                       // 32 blocks
#pragma unroll
        for (int rep = 0; rep < 4; rep++) {
            int eid = b * 1024 + rep * 256 + tid;
            int n = eid >> 8, k = eid & 255;
            g_woH[hidx(n, k, 16)] = __float2half_rn(w_out[(size_t)n * 256 + k]);
        }
    } else {
        for (int n = tid; n < G3; n += 256) {
            float acc = 0.f;
            const float* wr = w_ih + (size_t)n * DNF;
#pragma unroll 4
            for (int k = 0; k < DNF; k++) acc += wr[k] * b_msg[k];
            g_bvec[n] = acc;
        }
    }
}

// ---------------------------------------------------------------------------
// phase bodies (round-14, verbatim)
// ---------------------------------------------------------------------------
__device__ __forceinline__ void cei_body(char* S) {
    __half* sA  = (__half*)S;
    float*  red = (float*)(S + 4352);

    const int tid  = threadIdx.x;
    const int lane = tid & 31;
    const int w    = tid >> 5;
    const int nw   = w & 15;
    const int kh   = w >> 4;
    const int q    = lane >> 2, r = lane & 3;
    const int r0   = blockIdx.x * 16;

#pragma unroll
    for (int rep = 0; rep < 2; rep++) {
        int eid = tid + rep * 1024;
        int i = eid >> 7, d = eid & 127;
        sA[i * ALD + d] = __float2half_rn(g_er[(size_t)(r0 + i) * DNF + d]);
    }
    __syncthreads();

    const unsigned* Aw = (const unsigned*)sA;

    float acc[3][4];
#pragma unroll
    for (int j = 0; j < 3; j++)
#pragma unroll
        for (int c = 0; c < 4; c++) acc[j][c] = 0.f;

    const uint4* bp = (const uint4*)g_wieH;

    uint4 bf[2][3];
#pragma unroll
    for (int j = 0; j < 3; j++)
        bf[0][j] = bp[((kh * 2) * 48 + nw * 3 + j) * 32 + lane];

#pragma unroll
    for (int kk = 0; kk < 2; kk++) {
        const int u = kh * 2 + kk;
        const int cur = kk & 1, nxt = cur ^ 1;
        if (kk < 1) {
#pragma unroll
            for (int j = 0; j < 3; j++)
                bf[nxt][j] = bp[((u + 1) * 48 + nw * 3 + j) * 32 + lane];
        }
#pragma unroll
        for (int tk = 0; tk < 2; tk++) {
            const int off = (u * 2 + tk) * 8;
            unsigned a0 = Aw[q * 68 + off + r];
            unsigned a1 = Aw[(q + 8) * 68 + off + r];
            unsigned a2 = Aw[q * 68 + off + 4 + r];
            unsigned a3 = Aw[(q + 8) * 68 + off + 4 + r];
#pragma unroll
            for (int j = 0; j < 3; j++) {
                unsigned b0 = tk ? bf[cur][j].z : bf[cur][j].x;
                unsigned b1 = tk ? bf[cur][j].w : bf[cur][j].y;
                mma_f16(acc[j], a0, a1, a2, a3, b0, b1);
            }
        }
    }

    if (kh == 1) {
        float* rp = red + (nw * 32 + lane) * 13;
#pragma unroll
        for (int j = 0; j < 3; j++)
#pragma unroll
            for (int c = 0; c < 4; c++) rp[j * 4 + c] = acc[j][c];
    }
    __syncthreads();
    if (kh == 0) {
        const float* rp = red + (nw * 32 + lane) * 13;
#pragma unroll
        for (int j = 0; j < 3; j++) {
#pragma unroll
            for (int c = 0; c < 4; c++) acc[j][c] += rp[j * 4 + c];
            int col = (nw * 3 + j) * 8 + 2 * r;
            float bv0 = g_bvec[col], bv1 = g_bvec[col + 1];
            *(float2*)(g_cei + (size_t)(r0 + q) * G3 + col) =
                make_float2(acc[j][0] + bv0, acc[j][1] + bv1);
            *(float2*)(g_cei + (size_t)(r0 + q + 8) * G3 + col) =
                make_float2(acc[j][2] + bv0, acc[j][3] + bv1);
        }
    }
}

__device__ __forceinline__ void layer_body(char* S,
                                           const float* __restrict__ hprev,
                                           float* __restrict__ hnext,
                                           const float* __restrict__ b_ih,
                                           const float* __restrict__ b_hh) {
    __half* shA = (__half*)S;
    __half* hhA = (__half*)S + 16 * ALD;
    float*  gbi = (float*)S;
    float*  G   = (float*)(S + 8704);
    float4* ph  = (float4*)G;

    const int tid  = threadIdx.x;
    const int lane = tid & 31;
    const int w    = tid >> 5;
    const int q    = lane >> 2, r = lane & 3;
    const int r0   = blockIdx.x * 16;

    {
        const int row  = r0 + (w & 15);
        const int half = w >> 4;
        const int cnt  = g_nzc[row];
        const int2* ep = g_nze + (size_t)row * NN;
        ph[w * 32 + lane] = gather_half(hprev, ep, cnt, lane, half);
    }
    __syncthreads();

    if (w < 16) {
        float4 a = ph[w * 32 + lane];
        float4 b = ph[(w + 16) * 32 + lane];
        __half2* rp = (__half2*)(shA + w * ALD);
        rp[lane * 2]     = __floats2half2_rn(a.x + b.x, a.y + b.y);
        rp[lane * 2 + 1] = __floats2half2_rn(a.z + b.z, a.w + b.w);
    } else {
        int row = r0 + (w - 16);
        float4 hv = *(const float4*)(hprev + (size_t)row * DNF + lane * 4);
        __half2* rp = (__half2*)(hhA + (w - 16) * ALD);
        rp[lane * 2]     = __floats2half2_rn(hv.x, hv.y);
        rp[lane * 2 + 1] = __floats2half2_rn(hv.z, hv.w);
    }
    __syncthreads();

    const int mat = w >> 4;
    const int nw  = w & 15;
    const unsigned* Aw = (const unsigned*)(mat ? hhA : shA);
    const uint4* bp = (const uint4*)(mat ? g_whhH : g_wimH);

    float acc[3][4];
#pragma unroll
    for (int j = 0; j < 3; j++)
#pragma unroll
        for (int c = 0; c < 4; c++) acc[j][c] = 0.f;

    uint4 bf[2][3];
#pragma unroll
    for (int j = 0; j < 3; j++)
        bf[0][j] = bp[(0 * 48 + nw * 3 + j) * 32 + lane];

#pragma unroll
    for (int u = 0; u < 4; u++) {
        const int cur = u & 1, nxt = cur ^ 1;
        if (u < 3) {
#pragma unroll
            for (int j = 0; j < 3; j++)
                bf[nxt][j] = bp[((u + 1) * 48 + nw * 3 + j) * 32 + lane];
        }
#pragma unroll
        for (int tk = 0; tk < 2; tk++) {
            const int off = (u * 2 + tk) * 8;
            unsigned a0 = Aw[q * 68 + off + r];
            unsigned a1 = Aw[(q + 8) * 68 + off + r];
            unsigned a2 = Aw[q * 68 + off + 4 + r];
            unsigned a3 = Aw[(q + 8) * 68 + off + 4 + r];
#pragma unroll
            for (int j = 0; j < 3; j++) {
                unsigned b0 = tk ? bf[cur][j].z : bf[cur][j].x;
                unsigned b1 = tk ? bf[cur][j].w : bf[cur][j].y;
                mma_f16(acc[j], a0, a1, a2, a3, b0, b1);
            }
        }
    }

    if (mat == 1) {
#pragma unroll
        for (int j = 0; j < 3; j++) {
            int col = (nw * 3 + j) * 8 + 2 * r;
            float b0 = b_hh[col], b1 = b_hh[col + 1];
            G[q * GLD + col]           = acc[j][0] + b0;
            G[q * GLD + col + 1]       = acc[j][1] + b1;
            G[(q + 8) * GLD + col]     = acc[j][2] + b0;
            G[(q + 8) * GLD + col + 1] = acc[j][3] + b1;
        }
    }
    __syncthreads();

    if (mat == 0) {
#pragma unroll
        for (int j = 0; j < 3; j++) {
            int col = (nw * 3 + j) * 8 + 2 * r;
            float bi0 = b_ih[col], bi1 = b_ih[col + 1];
#pragma unroll
            for (int s = 0; s < 2; s++) {
                int i = q + s * 8;
                int row = r0 + i;
                float2 ce = *(const float2*)(g_cei + (size_t)row * G3 + col);
                float gi0 = acc[j][s * 2 + 0] + ce.x + bi0;
                float gi1 = acc[j][s * 2 + 1] + ce.y + bi1;
                if (col < 256) {
                    G[i * GLD + col]     += gi0;
                    G[i * GLD + col + 1] += gi1;
                } else {
                    gbi[i * GB_LD + (col - 256)]     = gi0;
                    gbi[i * GB_LD + (col - 256) + 1] = gi1;
                }
            }
        }
    }
    __syncthreads();

#pragma unroll
    for (int rep = 0; rep < 2; rep++) {
        int eid = tid + rep * 1024;
        int i = eid >> 7, d = eid & 127;
        int row = r0 + i;
        float rr = sigf(G[i * GLD + d]);
        float zz = sigf(G[i * GLD + 128 + d]);
        float nn = tanhf_fast(gbi[i * GB_LD + d] + rr * G[i * GLD + 256 + d]);
        float hold = hprev[(size_t)row * DNF + d];
        hnext[(size_t)row * DNF + d] = (1.0f - zz) * nn + zz * hold;
    }
}

__device__ __forceinline__ void readout_body(char* S,
        const float* __restrict__ hfin, const float* __restrict__ h0,
        const float* __restrict__ b_gate, const float* __restrict__ b_out,
        const float* __restrict__ w_embed, const float* __restrict__ edge,
        const float* __restrict__ w_fc, const float* __restrict__ b_fc,
        float* __restrict__ out, int* s_last) {
    float* sbuf = (float*)S;
    float* red  = (float*)(S + 16896);
    float* sred = (float*)(S + 35328);
    float* sgv  = (float*)(S + 39424);
    float* see  = (float*)(S + 39936);

    __half* hA0 = (__half*)sbuf;
    __half* hA1 = (__half*)sbuf + 16 * ALD;
    float* gp  = sbuf;
    float* op  = sbuf + 16 * GB_LD;

    const int tid  = threadIdx.x;
    const int lane = tid & 31;
    const int w    = tid >> 5;
    const int fg   = w & 7;
    const int mat  = (w >> 3) & 1;
    const int kh   = w >> 4;
    const int q    = lane >> 2, r = lane & 3;
    const int r0   = blockIdx.x * 16;

    {
        const float* src = (w < 16) ? hfin : h0;
        __half* dst = (w < 16) ? hA0 : hA1;
        int row = r0 + (w & 15);
        float4 v = *(const float4*)(src + (size_t)row * DNF + lane * 4);
        __half2* rp = (__half2*)(dst + (w & 15) * ALD);
        rp[lane * 2]     = __floats2half2_rn(v.x, v.y);
        rp[lane * 2 + 1] = __floats2half2_rn(v.z, v.w);
    }
    __syncthreads();

    const uint4* bp = (const uint4*)(mat ? g_woH : g_wgH);
    const unsigned* Aw = (const unsigned*)(kh ? hA1 : hA0);

    float acc[2][4];
#pragma unroll
    for (int j = 0; j < 2; j++)
#pragma unroll
        for (int c = 0; c < 4; c++) acc[j][c] = 0.f;

    uint4 bf[2][2];
#pragma unroll
    for (int j = 0; j < 2; j++)
        bf[0][j] = bp[((kh * 4) * 16 + fg * 2 + j) * 32 + lane];

#pragma unroll
    for (int kk = 0; kk < 4; kk++) {
        const int u = kh * 4 + kk;
        const int cur = kk & 1, nxt = cur ^ 1;
        if (kk < 3) {
#pragma unroll
            for (int j = 0; j < 2; j++)
                bf[nxt][j] = bp[((u + 1) * 16 + fg * 2 + j) * 32 + lane];
        }
#pragma unroll
        for (int tk = 0; tk < 2; tk++) {
            const int off = (kk * 2 + tk) * 8;
            unsigned a0 = Aw[q * 68 + off + r];
            unsigned a1 = Aw[(q + 8) * 68 + off + r];
            unsigned a2 = Aw[q * 68 + off + 4 + r];
            unsigned a3 = Aw[(q + 8) * 68 + off + 4 + r];
#pragma unroll
            for (int j = 0; j < 2; j++) {
                unsigned b0 = tk ? bf[cur][j].z : bf[cur][j].x;
                unsigned b1 = tk ? bf[cur][j].w : bf[cur][j].y;
                mma_f16(acc[j], a0, a1, a2, a3, b0, b1);
            }
        }
    }

    if (kh == 1) {
        float* rp = red + ((mat * 8 + fg) * 32 + lane) * 9;
#pragma unroll
        for (int j = 0; j < 2; j++)
#pragma unroll
            for (int c = 0; c < 4; c++) rp[j * 4 + c] = acc[j][c];
    }
    __syncthreads();
    if (kh == 0) {
        const float* rp = red + ((mat * 8 + fg) * 32 + lane) * 9;
        float* dst = mat ? op : gp;
        const float* bias = mat ? b_out : b_gate;
#pragma unroll
        for (int j = 0; j < 2; j++) {
#pragma unroll
            for (int c = 0; c < 4; c++) acc[j][c] += rp[j * 4 + c];
            int col = (fg * 2 + j) * 8 + 2 * r;
            float b0 = bias[col], b1 = bias[col + 1];
            dst[q * GB_LD + col]           = acc[j][0] + b0;
            dst[q * GB_LD + col + 1]       = acc[j][1] + b1;
            dst[(q + 8) * GB_LD + col]     = acc[j][2] + b0;
            dst[(q + 8) * GB_LD + col + 1] = acc[j][3] + b1;
        }
    }
    __syncthreads();

    {
        int grp = tid >> 7, d = tid & 127;
        float a = 0.f;
#pragma unroll
        for (int i = grp * 2; i < grp * 2 + 2; i++)
            a += sigf(gp[i * GB_LD + d]) * tanhf_fast(op[i * GB_LD + d]);
        sred[tid] = a;
    }
    __syncthreads();
    if (tid < 128) {
        float s = 0.f;
#pragma unroll
        for (int g = 0; g < 8; g++) s += sred[g * 128 + tid];
        g_part[blockIdx.x * DNF + tid] = s;
    }
    __syncthreads();

    if (tid == 0) {
        __threadfence();
        int old = atomicAdd(&g_rc, 1);
        *s_last = (old == NBLK - 1) ? 1 : 0;
        __threadfence();
    }
    __syncthreads();
    if (*s_last) {
        if (tid == 0) g_rc = 0;
        if (tid < 128) {
            float gv = 0.f;
            for (int b = 0; b < NBLK; b++) gv += g_part[b * DNF + tid];
            sgv[tid] = gv;
            float ee = 0.f;
#pragma unroll
            for (int f = 0; f < 5; f++) ee += w_embed[tid * 5 + f] * edge[f];
            see[tid] = ee;
        }
        __syncthreads();
        if (tid < 128) {
            float acc2 = b_fc[tid];
            const float* wr = w_fc + (size_t)tid * 256;
            for (int k = 0; k < 128; k++) acc2 += wr[k] * sgv[k];
            for (int k = 0; k < 128; k++) acc2 += wr[128 + k] * see[k];
            out[tid] = acc2;
        }
    }
}

// ---------------------------------------------------------------------------
// k_mega: cei | bar | 4x(layer | bar) | readout.  64 blocks x 1024 threads.
// ---------------------------------------------------------------------------
__global__ void __launch_bounds__(1024)
k_mega(const float* __restrict__ h_in,
       const float* __restrict__ b_ih,  const float* __restrict__ b_hh,
       const float* __restrict__ b_gate, const float* __restrict__ b_out,
       const float* __restrict__ w_embed, const float* __restrict__ edge,
       const float* __restrict__ w_fc,  const float* __restrict__ b_fc,
       float* __restrict__ out) {
    __shared__ __align__(16) char S[40960];
    __shared__ int s_last;

    cei_body(S);
    gbar(0);

    const float* hp[4] = { h_in, g_ha, g_hb, g_ha };
    float*       hn[4] = { g_ha, g_hb, g_ha, g_hb };
#pragma unroll 1
    for (int l = 0; l < 4; l++) {
        layer_body(S, hp[l], hn[l], b_ih, b_hh);
        gbar(1 + l);
    }

    readout_body(S, g_hb, h_in, b_gate, b_out, w_embed, edge,
                 w_fc, b_fc, out, &s_last);
}

// ---------------------------------------------------------------------------
extern "C" void kernel_launch(void* const* d_in, const int* in_sizes, int n_in,
                              void* d_out, int out_size) {
    const float* h_in    = (const float*)d_in[0];
    const float* e       = (const float*)d_in[1];
    const float* adj     = (const float*)d_in[2];
    const float* edge    = (const float*)d_in[3];
    const float* w_msg_h = (const float*)d_in[4];
    const float* w_msg_e = (const float*)d_in[5];
    const float* b_msg   = (const float*)d_in[6];
    const float* w_ih    = (const float*)d_in[7];
    const float* w_hh    = (const float*)d_in[8];
    const float* b_ih    = (const float*)d_in[9];
    const float* b_hh    = (const float*)d_in[10];
    const float* w_gate  = (const float*)d_in[11];
    const float* b_gate  = (const float*)d_in[12];
    const float* w_out   = (const float*)d_in[13];
    const float* b_out   = (const float*)d_in[14];
    const float* w_embed = (const float*)d_in[15];
    const float* w_fc    = (const float*)d_in[16];
    const float* b_fc    = (const float*)d_in[17];
    float* out = (float*)d_out;

    k_setup<<<NN + 241, 256>>>(adj, e, w_msg_h, w_msg_e, w_ih, b_msg,
                               w_hh, w_gate, w_out);
    k_mega<<<NBLK, 1024>>>(h_in, b_ih, b_hh, b_gate, b_out,
                           w_embed, edge, w_fc, b_fc, out);
}

// round 17
// speedup vs baseline: 1.2379x; 1.0212x over previous
#include <cuda_runtime.h>
#include <cuda_fp16.h>
#include <math.h>

#define NN   1024
#define DNF  128
#define G3   384
#define ALD  136
#define GLD  388
#define GB_LD 132
#define LOG2E 1.4426950408889634f
#define NBLK 64

// ---------------- device scratch ----------------
__device__ float g_er  [NN * DNF];
__device__ float g_cei [NN * G3];
__device__ float g_ha  [NN * DNF];
__device__ float g_hb  [NN * DNF];
__device__ __half g_wimH[G3 * DNF];
__device__ __half g_wieH[G3 * DNF];
__device__ __half g_whhH[G3 * DNF];
__device__ __half g_wgH [DNF * 256];
__device__ __half g_woH [DNF * 256];
__device__ float g_bvec[G3];
__device__ int2  g_nze [NN * NN];
__device__ int   g_nzc [NN];
__device__ float g_part[NBLK * DNF];
__device__ int   g_rc;
__device__ int   g_bin [8];
__device__ int   g_bout[8];

// ---------------- fast transcendentals --------
__device__ __forceinline__ float fex2(float x) {
    float r; asm("ex2.approx.f32 %0, %1;" : "=f"(r) : "f"(x)); return r;
}
__device__ __forceinline__ float frcp(float x) {
    float r; asm("rcp.approx.f32 %0, %1;" : "=f"(r) : "f"(x)); return r;
}
__device__ __forceinline__ float sigf(float x) {
    return frcp(1.0f + fex2(-x * LOG2E));
}
__device__ __forceinline__ float tanhf_fast(float x) {
    return 1.0f - 2.0f * frcp(1.0f + fex2(x * (2.0f * LOG2E)));
}

__device__ __forceinline__ void mma_f16(float* c,
                                        unsigned a0, unsigned a1,
                                        unsigned a2, unsigned a3,
                                        unsigned b0, unsigned b1) {
    asm volatile(
        "mma.sync.aligned.m16n8k16.row.col.f32.f16.f16.f32 "
        "{%0,%1,%2,%3}, {%4,%5,%6,%7}, {%8,%9}, {%0,%1,%2,%3};"
        : "+f"(c[0]), "+f"(c[1]), "+f"(c[2]), "+f"(c[3])
        : "r"(a0), "r"(a1), "r"(a2), "r"(a3), "r"(b0), "r"(b1));
}

// fp16 frag-packed index (round-11 layout)
__device__ __forceinline__ int hidx(int n, int k, int nfr) {
    int f = n >> 3, q = n & 7;
    int t = k >> 4, kk = k & 15;
    int half = kk >> 3;
    int r = (kk & 7) >> 1;
    int lo = kk & 1;
    int u = t >> 1, tk = t & 1;
    return ((((u * nfr + f) * 32 + q * 4 + r) * 4) + tk * 2 + half) * 2 + lo;
}

// grid barrier across NBLK blocks (round-14 validated)
__device__ __forceinline__ void gbar(int k) {
    __syncthreads();
    if (threadIdx.x == 0) {
        __threadfence();
        atomicAdd(&g_bin[k], 1);
        while (((volatile int*)g_bin)[k] < NBLK) { }
        int o = atomicAdd(&g_bout[k], 1);
        if (o == NBLK - 1) { g_bin[k] = 0; g_bout[k] = 0; }
        __threadfence();
    }
    __syncthreads();
}

// strided warp gather (stride 2, start = half), 8 gathers in flight
__device__ __forceinline__ float4 gather_half(const float* __restrict__ src,
                                              const int2* __restrict__ ep,
                                              int cnt, int lane, int half) {
    float4 acc = make_float4(0.f, 0.f, 0.f, 0.f);
    int k = half;
    for (; k + 14 < cnt; k += 16) {
        int2 e[8];
#pragma unroll
        for (int u = 0; u < 8; u++) e[u] = ep[k + 2 * u];
        float4 a[8];
#pragma unroll
        for (int u = 0; u < 8; u++)
            a[u] = *(const float4*)(src + (size_t)e[u].x * DNF + lane * 4);
#pragma unroll
        for (int u = 0; u < 8; u++) {
            float w = __int_as_float(e[u].y);
            acc.x += w * a[u].x; acc.y += w * a[u].y;
            acc.z += w * a[u].z; acc.w += w * a[u].w;
        }
    }
    for (; k < cnt; k += 2) {
        int2 e = ep[k];
        float w = __int_as_float(e.y);
        float4 av = *(const float4*)(src + (size_t)e.x * DNF + lane * 4);
        acc.x += w*av.x; acc.y += w*av.y; acc.z += w*av.z; acc.w += w*av.w;
    }
    return acc;
}

// ---------------------------------------------------------------------------
// k_setup: bid<1024 — block/row compaction + 8-warp e-reduce.
// bid>=1024: 128 blocks weight products (unroll-16 MLP), packs, bvec.
// ---------------------------------------------------------------------------
__global__ void __launch_bounds__(256)
k_setup(const float* __restrict__ adj, const float* __restrict__ e,
        const float* __restrict__ w_msg_h, const float* __restrict__ w_msg_e,
        const float* __restrict__ w_ih, const float* __restrict__ b_msg,
        const float* __restrict__ w_hh, const float* __restrict__ w_gate,
        const float* __restrict__ w_out) {
    const int bid = blockIdx.x;
    const int tid = threadIdx.x;

    if (bid < NN) {
        const int i    = bid;
        const int lane = tid & 31;
        const int w    = tid >> 5;

        __shared__ int   s_idx[NN];
        __shared__ float s_val[NN];
        __shared__ int   s_wcnt[8];
        __shared__ int   s_woff[8];
        __shared__ int   s_cnt;
        __shared__ float s_red[8 * DNF];

        const float* arow = adj + (size_t)i * NN;
        const int base = w * 128;

        float av[4]; unsigned mm[4];
#pragma unroll
        for (int c = 0; c < 4; c++) av[c] = arow[base + c * 32 + lane];
        int tot = 0;
#pragma unroll
        for (int c = 0; c < 4; c++) {
            mm[c] = __ballot_sync(0xffffffffu, av[c] != 0.0f);
            tot += __popc(mm[c]);
        }
        if (lane == 0) s_wcnt[w] = tot;
        __syncthreads();
        if (tid == 0) {
            int run = 0;
            for (int ww = 0; ww < 8; ww++) { s_woff[ww] = run; run += s_wcnt[ww]; }
            s_cnt = run;
        }
        __syncthreads();

        int off = s_woff[w];
        const unsigned lm = (1u << lane) - 1u;
#pragma unroll
        for (int c = 0; c < 4; c++) {
            if (av[c] != 0.0f) {
                int p = off + __popc(mm[c] & lm);
                s_idx[p] = base + c * 32 + lane;
                s_val[p] = av[c];
            }
            off += __popc(mm[c]);
        }
        __syncthreads();

        const int cnt = s_cnt;
        if (tid == 0) g_nzc[i] = cnt;
        for (int k = tid; k < cnt; k += 256)
            g_nze[(size_t)i * NN + k] = make_int2(s_idx[k],
                                                  __float_as_int(s_val[k]));

        const int q = tid & 31;
        const int g = tid >> 5;
        const float* ebase = e + (size_t)i * NN * DNF;
        float4 acc = make_float4(0.f, 0.f, 0.f, 0.f);
        for (int k = g; k < cnt; k += 8) {
            float v = s_val[k];
            float4 ev = *(const float4*)(ebase + (size_t)s_idx[k] * DNF + q * 4);
            acc.x += v * ev.x; acc.y += v * ev.y;
            acc.z += v * ev.z; acc.w += v * ev.w;
        }
        s_red[g * DNF + q * 4 + 0] = acc.x;
        s_red[g * DNF + q * 4 + 1] = acc.y;
        s_red[g * DNF + q * 4 + 2] = acc.z;
        s_red[g * DNF + q * 4 + 3] = acc.w;
        __syncthreads();
        if (tid < 128) {
            float s = 0.f;
#pragma unroll
            for (int gg = 0; gg < 8; gg++) s += s_red[gg * DNF + tid];
            g_er[(size_t)i * DNF + tid] = s;
        }
        return;
    }

    const int sid = bid - NN;
    if (sid < 128) {
        // ---- wim/wie products, B-reuse + deep unroll (MLP 16) ----
        const int lane = tid & 31;
        const int w    = tid >> 5;
        const int ww   = sid * 8 + w;
        const int m    = ww >> 9;
        const int widx = ww & 511;
        const int n0   = (widx >> 2) * 3;
        const int kk   = (widx & 3) * 32 + lane;
        const float* B = m ? w_msg_e : w_msg_h;
        __half* P = m ? g_wieH : g_wimH;
        const float* w0 = w_ih + (size_t)(n0 + 0) * DNF;
        const float* w1 = w_ih + (size_t)(n0 + 1) * DNF;
        const float* w2 = w_ih + (size_t)(n0 + 2) * DNF;
        float a0 = 0.f, a1 = 0.f, a2 = 0.f;
#pragma unroll
        for (int dd = 0; dd < DNF; dd += 16) {
            float bb[16];
#pragma unroll
            for (int u = 0; u < 16; u++) bb[u] = B[(size_t)(dd + u) * DNF + kk];
#pragma unroll
            for (int u = 0; u < 16; u++) {
                a0 += w0[dd + u] * bb[u];
                a1 += w1[dd + u] * bb[u];
                a2 += w2[dd + u] * bb[u];
            }
        }
        P[hidx(n0 + 0, kk, 48)] = __float2half_rn(a0);
        P[hidx(n0 + 1, kk, 48)] = __float2half_rn(a1);
        P[hidx(n0 + 2, kk, 48)] = __float2half_rn(a2);
    } else if (sid < 176) {
        int b = sid - 128;
#pragma unroll
        for (int rep = 0; rep < 4; rep++) {
            int eid = b * 1024 + rep * 256 + tid;
            int n = eid >> 7, k = eid & 127;
            g_whhH[hidx(n, k, 48)] = __float2half_rn(w_hh[(size_t)n * DNF + k]);
        }
    } else if (sid < 208) {
        int b = sid - 176;
#pragma unroll
        for (int rep = 0; rep < 4; rep++) {
            int eid = b * 1024 + rep * 256 + tid;
            int n = eid >> 8, k = eid & 255;
            g_wgH[hidx(n, k, 16)] = __float2half_rn(w_gate[(size_t)n * 256 + k]);
        }
    } else if (sid < 240) {
        int b = sid - 208;
#pragma unroll
        for (int rep = 0; rep < 4; rep++) {
            int eid = b * 1024 + rep * 256 + tid;
            int n = eid >> 8, k = eid & 255;
            g_woH[hidx(n, k, 16)] = __float2half_rn(w_out[(size_t)n * 256 + k]);
        }
    } else {
        for (int n = tid; n < G3; n += 256) {
            float acc = 0.f;
            const float* wr = w_ih + (size_t)n * DNF;
#pragma unroll 16
            for (int k = 0; k < DNF; k++) acc += wr[k] * b_msg[k];
            g_bvec[n] = acc;
        }
    }
}

// ---------------------------------------------------------------------------
// phase bodies (round-14, verbatim except gather)
// ---------------------------------------------------------------------------
__device__ __forceinline__ void cei_body(char* S) {
    __half* sA  = (__half*)S;
    float*  red = (float*)(S + 4352);

    const int tid  = threadIdx.x;
    const int lane = tid & 31;
    const int w    = tid >> 5;
    const int nw   = w & 15;
    const int kh   = w >> 4;
    const int q    = lane >> 2, r = lane & 3;
    const int r0   = blockIdx.x * 16;

#pragma unroll
    for (int rep = 0; rep < 2; rep++) {
        int eid = tid + rep * 1024;
        int i = eid >> 7, d = eid & 127;
        sA[i * ALD + d] = __float2half_rn(g_er[(size_t)(r0 + i) * DNF + d]);
    }
    __syncthreads();

    const unsigned* Aw = (const unsigned*)sA;

    float acc[3][4];
#pragma unroll
    for (int j = 0; j < 3; j++)
#pragma unroll
        for (int c = 0; c < 4; c++) acc[j][c] = 0.f;

    const uint4* bp = (const uint4*)g_wieH;

    uint4 bf[2][3];
#pragma unroll
    for (int j = 0; j < 3; j++)
        bf[0][j] = bp[((kh * 2) * 48 + nw * 3 + j) * 32 + lane];

#pragma unroll
    for (int kk = 0; kk < 2; kk++) {
        const int u = kh * 2 + kk;
        const int cur = kk & 1, nxt = cur ^ 1;
        if (kk < 1) {
#pragma unroll
            for (int j = 0; j < 3; j++)
                bf[nxt][j] = bp[((u + 1) * 48 + nw * 3 + j) * 32 + lane];
        }
#pragma unroll
        for (int tk = 0; tk < 2; tk++) {
            const int off = (u * 2 + tk) * 8;
            unsigned a0 = Aw[q * 68 + off + r];
            unsigned a1 = Aw[(q + 8) * 68 + off + r];
            unsigned a2 = Aw[q * 68 + off + 4 + r];
            unsigned a3 = Aw[(q + 8) * 68 + off + 4 + r];
#pragma unroll
            for (int j = 0; j < 3; j++) {
                unsigned b0 = tk ? bf[cur][j].z : bf[cur][j].x;
                unsigned b1 = tk ? bf[cur][j].w : bf[cur][j].y;
                mma_f16(acc[j], a0, a1, a2, a3, b0, b1);
            }
        }
    }

    if (kh == 1) {
        float* rp = red + (nw * 32 + lane) * 13;
#pragma unroll
        for (int j = 0; j < 3; j++)
#pragma unroll
            for (int c = 0; c < 4; c++) rp[j * 4 + c] = acc[j][c];
    }
    __syncthreads();
    if (kh == 0) {
        const float* rp = red + (nw * 32 + lane) * 13;
#pragma unroll
        for (int j = 0; j < 3; j++) {
#pragma unroll
            for (int c = 0; c < 4; c++) acc[j][c] += rp[j * 4 + c];
            int col = (nw * 3 + j) * 8 + 2 * r;
            float bv0 = g_bvec[col], bv1 = g_bvec[col + 1];
            *(float2*)(g_cei + (size_t)(r0 + q) * G3 + col) =
                make_float2(acc[j][0] + bv0, acc[j][1] + bv1);
            *(float2*)(g_cei + (size_t)(r0 + q + 8) * G3 + col) =
                make_float2(acc[j][2] + bv0, acc[j][3] + bv1);
        }
    }
}

__device__ __forceinline__ void layer_body(char* S,
                                           const float* __restrict__ hprev,
                                           float* __restrict__ hnext,
                                           const float* __restrict__ b_ih,
                                           const float* __restrict__ b_hh) {
    __half* shA = (__half*)S;
    __half* hhA = (__half*)S + 16 * ALD;
    float*  gbi = (float*)S;
    float*  G   = (float*)(S + 8704);
    float4* ph  = (float4*)G;

    const int tid  = threadIdx.x;
    const int lane = tid & 31;
    const int w    = tid >> 5;
    const int q    = lane >> 2, r = lane & 3;
    const int r0   = blockIdx.x * 16;

    {
        const int row  = r0 + (w & 15);
        const int half = w >> 4;
        const int cnt  = g_nzc[row];
        const int2* ep = g_nze + (size_t)row * NN;
        ph[w * 32 + lane] = gather_half(hprev, ep, cnt, lane, half);
    }
    __syncthreads();

    if (w < 16) {
        float4 a = ph[w * 32 + lane];
        float4 b = ph[(w + 16) * 32 + lane];
        __half2* rp = (__half2*)(shA + w * ALD);
        rp[lane * 2]     = __floats2half2_rn(a.x + b.x, a.y + b.y);
        rp[lane * 2 + 1] = __floats2half2_rn(a.z + b.z, a.w + b.w);
    } else {
        int row = r0 + (w - 16);
        float4 hv = *(const float4*)(hprev + (size_t)row * DNF + lane * 4);
        __half2* rp = (__half2*)(hhA + (w - 16) * ALD);
        rp[lane * 2]     = __floats2half2_rn(hv.x, hv.y);
        rp[lane * 2 + 1] = __floats2half2_rn(hv.z, hv.w);
    }
    __syncthreads();

    const int mat = w >> 4;
    const int nw  = w & 15;
    const unsigned* Aw = (const unsigned*)(mat ? hhA : shA);
    const uint4* bp = (const uint4*)(mat ? g_whhH : g_wimH);

    float acc[3][4];
#pragma unroll
    for (int j = 0; j < 3; j++)
#pragma unroll
        for (int c = 0; c < 4; c++) acc[j][c] = 0.f;

    uint4 bf[2][3];
#pragma unroll
    for (int j = 0; j < 3; j++)
        bf[0][j] = bp[(0 * 48 + nw * 3 + j) * 32 + lane];

#pragma unroll
    for (int u = 0; u < 4; u++) {
        const int cur = u & 1, nxt = cur ^ 1;
        if (u < 3) {
#pragma unroll
            for (int j = 0; j < 3; j++)
                bf[nxt][j] = bp[((u + 1) * 48 + nw * 3 + j) * 32 + lane];
        }
#pragma unroll
        for (int tk = 0; tk < 2; tk++) {
            const int off = (u * 2 + tk) * 8;
            unsigned a0 = Aw[q * 68 + off + r];
            unsigned a1 = Aw[(q + 8) * 68 + off + r];
            unsigned a2 = Aw[q * 68 + off + 4 + r];
            unsigned a3 = Aw[(q + 8) * 68 + off + 4 + r];
#pragma unroll
            for (int j = 0; j < 3; j++) {
                unsigned b0 = tk ? bf[cur][j].z : bf[cur][j].x;
                unsigned b1 = tk ? bf[cur][j].w : bf[cur][j].y;
                mma_f16(acc[j], a0, a1, a2, a3, b0, b1);
            }
        }
    }

    if (mat == 1) {
#pragma unroll
        for (int j = 0; j < 3; j++) {
            int col = (nw * 3 + j) * 8 + 2 * r;
            float b0 = b_hh[col], b1 = b_hh[col + 1];
            G[q * GLD + col]           = acc[j][0] + b0;
            G[q * GLD + col + 1]       = acc[j][1] + b1;
            G[(q + 8) * GLD + col]     = acc[j][2] + b0;
            G[(q + 8) * GLD + col + 1] = acc[j][3] + b1;
        }
    }
    __syncthreads();

    if (mat == 0) {
#pragma unroll
        for (int j = 0; j < 3; j++) {
            int col = (nw * 3 + j) * 8 + 2 * r;
            float bi0 = b_ih[col], bi1 = b_ih[col + 1];
#pragma unroll
            for (int s = 0; s < 2; s++) {
                int i = q + s * 8;
                int row = r0 + i;
                float2 ce = *(const float2*)(g_cei + (size_t)row * G3 + col);
                float gi0 = acc[j][s * 2 + 0] + ce.x + bi0;
                float gi1 = acc[j][s * 2 + 1] + ce.y + bi1;
                if (col < 256) {
                    G[i * GLD + col]     += gi0;
                    G[i * GLD + col + 1] += gi1;
                } else {
                    gbi[i * GB_LD + (col - 256)]     = gi0;
                    gbi[i * GB_LD + (col - 256) + 1] = gi1;
                }
            }
        }
    }
    __syncthreads();

#pragma unroll
    for (int rep = 0; rep < 2; rep++) {
        int eid = tid + rep * 1024;
        int i = eid >> 7, d = eid & 127;
        int row = r0 + i;
        float rr = sigf(G[i * GLD + d]);
        float zz = sigf(G[i * GLD + 128 + d]);
        float nn = tanhf_fast(gbi[i * GB_LD + d] + rr * G[i * GLD + 256 + d]);
        float hold = hprev[(size_t)row * DNF + d];
        hnext[(size_t)row * DNF + d] = (1.0f - zz) * nn + zz * hold;
    }
}

__device__ __forceinline__ void readout_body(char* S,
        const float* __restrict__ hfin, const float* __restrict__ h0,
        const float* __restrict__ b_gate, const float* __restrict__ b_out,
        const float* __restrict__ w_embed, const float* __restrict__ edge,
        const float* __restrict__ w_fc, const float* __restrict__ b_fc,
        float* __restrict__ out, int* s_last) {
    float* sbuf = (float*)S;
    float* red  = (float*)(S + 16896);
    float* sred = (float*)(S + 35328);
    float* sgv  = (float*)(S + 39424);
    float* see  = (float*)(S + 39936);

    __half* hA0 = (__half*)sbuf;
    __half* hA1 = (__half*)sbuf + 16 * ALD;
    float* gp  = sbuf;
    float* op  = sbuf + 16 * GB_LD;

    const int tid  = threadIdx.x;
    const int lane = tid & 31;
    const int w    = tid >> 5;
    const int fg   = w & 7;
    const int mat  = (w >> 3) & 1;
    const int kh   = w >> 4;
    const int q    = lane >> 2, r = lane & 3;
    const int r0   = blockIdx.x * 16;

    {
        const float* src = (w < 16) ? hfin : h0;
        __half* dst = (w < 16) ? hA0 : hA1;
        int row = r0 + (w & 15);
        float4 v = *(const float4*)(src + (size_t)row * DNF + lane * 4);
        __half2* rp = (__half2*)(dst + (w & 15) * ALD);
        rp[lane * 2]     = __floats2half2_rn(v.x, v.y);
        rp[lane * 2 + 1] = __floats2half2_rn(v.z, v.w);
    }
    __syncthreads();

    const uint4* bp = (const uint4*)(mat ? g_woH : g_wgH);
    const unsigned* Aw = (const unsigned*)(kh ? hA1 : hA0);

    float acc[2][4];
#pragma unroll
    for (int j = 0; j < 2; j++)
#pragma unroll
        for (int c = 0; c < 4; c++) acc[j][c] = 0.f;

    uint4 bf[2][2];
#pragma unroll
    for (int j = 0; j < 2; j++)
        bf[0][j] = bp[((kh * 4) * 16 + fg * 2 + j) * 32 + lane];

#pragma unroll
    for (int kk = 0; kk < 4; kk++) {
        const int u = kh * 4 + kk;
        const int cur = kk & 1, nxt = cur ^ 1;
        if (kk < 3) {
#pragma unroll
            for (int j = 0; j < 2; j++)
                bf[nxt][j] = bp[((u + 1) * 16 + fg * 2 + j) * 32 + lane];
        }
#pragma unroll
        for (int tk = 0; tk < 2; tk++) {
            const int off = (kk * 2 + tk) * 8;
            unsigned a0 = Aw[q * 68 + off + r];
            unsigned a1 = Aw[(q + 8) * 68 + off + r];
            unsigned a2 = Aw[q * 68 + off + 4 + r];
            unsigned a3 = Aw[(q + 8) * 68 + off + 4 + r];
#pragma unroll
            for (int j = 0; j < 2; j++) {
                unsigned b0 = tk ? bf[cur][j].z : bf[cur][j].x;
                unsigned b1 = tk ? bf[cur][j].w : bf[cur][j].y;
                mma_f16(acc[j], a0, a1, a2, a3, b0, b1);
            }
        }
    }

    if (kh == 1) {
        float* rp = red + ((mat * 8 + fg) * 32 + lane) * 9;
#pragma unroll
        for (int j = 0; j < 2; j++)
#pragma unroll
            for (int c = 0; c < 4; c++) rp[j * 4 + c] = acc[j][c];
    }
    __syncthreads();
    if (kh == 0) {
        const float* rp = red + ((mat * 8 + fg) * 32 + lane) * 9;
        float* dst = mat ? op : gp;
        const float* bias = mat ? b_out : b_gate;
#pragma unroll
        for (int j = 0; j < 2; j++) {
#pragma unroll
            for (int c = 0; c < 4; c++) acc[j][c] += rp[j * 4 + c];
            int col = (fg * 2 + j) * 8 + 2 * r;
            float b0 = bias[col], b1 = bias[col + 1];
            dst[q * GB_LD + col]           = acc[j][0] + b0;
            dst[q * GB_LD + col + 1]       = acc[j][1] + b1;
            dst[(q + 8) * GB_LD + col]     = acc[j][2] + b0;
            dst[(q + 8) * GB_LD + col + 1] = acc[j][3] + b1;
        }
    }
    __syncthreads();

    {
        int grp = tid >> 7, d = tid & 127;
        float a = 0.f;
#pragma unroll
        for (int i = grp * 2; i < grp * 2 + 2; i++)
            a += sigf(gp[i * GB_LD + d]) * tanhf_fast(op[i * GB_LD + d]);
        sred[tid] = a;
    }
    __syncthreads();
    if (tid < 128) {
        float s = 0.f;
#pragma unroll
        for (int g = 0; g < 8; g++) s += sred[g * 128 + tid];
        g_part[blockIdx.x * DNF + tid] = s;
    }
    __syncthreads();

    if (tid == 0) {
        __threadfence();
        int old = atomicAdd(&g_rc, 1);
        *s_last = (old == NBLK - 1) ? 1 : 0;
        __threadfence();
    }
    __syncthreads();
    if (*s_last) {
        if (tid == 0) g_rc = 0;
        if (tid < 128) {
            float gv = 0.f;
            for (int b = 0; b < NBLK; b++) gv += g_part[b * DNF + tid];
            sgv[tid] = gv;
            float ee = 0.f;
#pragma unroll
            for (int f = 0; f < 5; f++) ee += w_embed[tid * 5 + f] * edge[f];
            see[tid] = ee;
        }
        __syncthreads();
        if (tid < 128) {
            float acc2 = b_fc[tid];
            const float* wr = w_fc + (size_t)tid * 256;
            for (int k = 0; k < 128; k++) acc2 += wr[k] * sgv[k];
            for (int k = 0; k < 128; k++) acc2 += wr[128 + k] * see[k];
            out[tid] = acc2;
        }
    }
}

// ---------------------------------------------------------------------------
// k_mega: cei | bar | 4x(layer | bar) | readout.  64 blocks x 1024 threads.
// ---------------------------------------------------------------------------
__global__ void __launch_bounds__(1024)
k_mega(const float* __restrict__ h_in,
       const float* __restrict__ b_ih,  const float* __restrict__ b_hh,
       const float* __restrict__ b_gate, const float* __restrict__ b_out,
       const float* __restrict__ w_embed, const float* __restrict__ edge,
       const float* __restrict__ w_fc,  const float* __restrict__ b_fc,
       float* __restrict__ out) {
    __shared__ __align__(16) char S[40960];
    __shared__ int s_last;

    cei_body(S);
    gbar(0);

    const float* hp[4] = { h_in, g_ha, g_hb, g_ha };
    float*       hn[4] = { g_ha, g_hb, g_ha, g_hb };
#pragma unroll 1
    for (int l = 0; l < 4; l++) {
        layer_body(S, hp[l], hn[l], b_ih, b_hh);
        gbar(1 + l);
    }

    readout_body(S, g_hb, h_in, b_gate, b_out, w_embed, edge,
                 w_fc, b_fc, out, &s_last);
}

// ---------------------------------------------------------------------------
extern "C" void kernel_launch(void* const* d_in, const int* in_sizes, int n_in,
                              void* d_out, int out_size) {
    const float* h_in    = (const float*)d_in[0];
    const float* e       = (const float*)d_in[1];
    const float* adj     = (const float*)d_in[2];
    const float* edge    = (const float*)d_in[3];
    const float* w_msg_h = (const float*)d_in[4];
    const float* w_msg_e = (const float*)d_in[5];
    const float* b_msg   = (const float*)d_in[6];
    const float* w_ih    = (const float*)d_in[7];
    const float* w_hh    = (const float*)d_in[8];
    const float* b_ih    = (const float*)d_in[9];
    const float* b_hh    = (const float*)d_in[10];
    const float* w_gate  = (const float*)d_in[11];
    const float* b_gate  = (const float*)d_in[12];
    const float* w_out   = (const float*)d_in[13];
    const float* b_out   = (const float*)d_in[14];
    const float* w_embed = (const float*)d_in[15];
    const float* w_fc    = (const float*)d_in[16];
    const float* b_fc    = (const float*)d_in[17];
    float* out = (float*)d_out;

    k_setup<<<NN + 241, 256>>>(adj, e, w_msg_h, w_msg_e, w_ih, b_msg,
                               w_hh, w_gate, w_out);
    k_mega<<<NBLK, 1024>>>(h_in, b_ih, b_hh, b_gate, b_out,
                           w_embed, edge, w_fc, b_fc, out);
}